// round 14
// baseline (speedup 1.0000x reference)
#include <cuda_runtime.h>

// Problem constants (fixed by the reference)
#define BB 8
#define SS 8192
#define DD 768
#define VV 64
#define LL 26
#define NSEG (BB * VV)      // 512
#define NTHR 384            // 12 warps
#define NW   12
#define NI4  (SS / 4)       // 2048 int4 per batch
#define PERW ((NI4 + NW - 1) / NW)   // 171 int4 per warp

// Single kernel, one CTA per (batch, symbol) segment, fused scan+gather:
// each warp scans a contiguous ids slice and immediately gathers matching
// rows warp-cooperatively into private registers (no smem list, no barrier
// between scan and gather, scan/gather loads interleave in one stream).
__global__ __launch_bounds__(NTHR, 4) void k_fused(
    const float* __restrict__ h,      // [B*S, D]
    const int*   __restrict__ ids,    // [B*S]
    const float* __restrict__ Wm,     // [L, D]
    const float* __restrict__ bias,   // [L]
    float* __restrict__ out)          // [B, V, L]
{
    const int seg  = blockIdx.x;
    const int b    = seg >> 6;
    const int v    = seg & (VV - 1);
    const int tid  = threadIdx.x;
    const int warp = tid >> 5;         // 0..11
    const int lane = tid & 31;

    __shared__ float4 spart[NW][DD / 4];   // 36 KB warp partials
    __shared__ int    swcnt[NW];

    // Masked symbol 0: write zeros, leave.
    if (v == 0) {
        if (tid < LL) out[seg * LL + tid] = 0.0f;
        return;
    }

    // ---- Fused scan + gather (warp-private) ----
    float4 a0 = make_float4(0.f, 0.f, 0.f, 0.f);
    float4 a1 = a0, a2 = a0, a3 = a0, a4 = a0, a5 = a0;
    int mycnt = 0;
    {
        const int4* __restrict__ idb4 = (const int4*)(ids + b * SS);
        // Row base for this lane: lane-th float4 of the row.
        const float4* __restrict__ hb =
            (const float4*)h + (long)b * SS * (DD / 4) + lane;
        const int q0 = warp * PERW;
        const int q1 = (q0 + PERW < NI4) ? (q0 + PERW) : NI4;

        for (int base = q0; base < q1; base += 32) {
            const int  q     = base + lane;
            const bool valid = (q < q1);
            int4 w4 = make_int4(-1, -1, -1, -1);
            if (valid) w4 = __ldg(&idb4[q]);

            #pragma unroll
            for (int c = 0; c < 4; ++c) {
                const int idv = (c == 0) ? w4.x : (c == 1) ? w4.y
                              : (c == 2) ? w4.z : w4.w;
                unsigned bal = __ballot_sync(0xffffffffu, idv == v);
                mycnt += __popc(bal);
                while (bal) {
                    const int src = __ffs(bal) - 1;
                    bal &= bal - 1;
                    const int tok = __shfl_sync(0xffffffffu, q, src) * 4 + c;
                    const float4* __restrict__ r = hb + (long)tok * (DD / 4);
                    float4 t0 = __ldg(r);
                    float4 t1 = __ldg(r + 32);
                    float4 t2 = __ldg(r + 64);
                    float4 t3 = __ldg(r + 96);
                    float4 t4 = __ldg(r + 128);
                    float4 t5 = __ldg(r + 160);
                    a0.x += t0.x; a0.y += t0.y; a0.z += t0.z; a0.w += t0.w;
                    a1.x += t1.x; a1.y += t1.y; a1.z += t1.z; a1.w += t1.w;
                    a2.x += t2.x; a2.y += t2.y; a2.z += t2.z; a2.w += t2.w;
                    a3.x += t3.x; a3.y += t3.y; a3.z += t3.z; a3.w += t3.w;
                    a4.x += t4.x; a4.y += t4.y; a4.z += t4.z; a4.w += t4.w;
                    a5.x += t5.x; a5.y += t5.y; a5.z += t5.z; a5.w += t5.w;
                }
            }
        }
    }
    // Stage warp partials.
    spart[warp][lane +   0] = a0;
    spart[warp][lane +  32] = a1;
    spart[warp][lane +  64] = a2;
    spart[warp][lane +  96] = a3;
    spart[warp][lane + 128] = a4;
    spart[warp][lane + 160] = a5;
    if (lane == 0) swcnt[warp] = mycnt;
    __syncthreads();

    // ---- Reduce 12 warp partials into spart[0] (192 threads) ----
    if (tid < DD / 4) {
        float4 s = spart[0][tid];
        #pragma unroll
        for (int w = 1; w < NW; ++w) {
            float4 t = spart[w][tid];
            s.x += t.x; s.y += t.y; s.z += t.z; s.w += t.w;
        }
        spart[0][tid] = s;
    }
    __syncthreads();

    int cnt = 0;
    #pragma unroll
    for (int w = 0; w < NW; ++w) cnt += swcnt[w];

    // ---- Mean + linear head (12 warps over 26 labels) ----
    const float* __restrict__ ssum = (const float*)spart;   // 768 floats
    const bool  active = (cnt > 0);
    const float inv    = 1.0f / (float)(cnt > 0 ? cnt : 1);

    for (int l = warp; l < LL; l += NW) {
        float s = 0.f;
        #pragma unroll
        for (int k = lane; k < DD; k += 32)
            s += ssum[k] * __ldg(&Wm[l * DD + k]);
        #pragma unroll
        for (int o = 16; o; o >>= 1)
            s += __shfl_xor_sync(0xffffffffu, s, o);
        if (lane == 0)
            out[seg * LL + l] = active ? (s * inv + __ldg(&bias[l])) : 0.0f;
    }
}

// ---------------------------------------------------------------------------
extern "C" void kernel_launch(void* const* d_in, const int* in_sizes, int n_in,
                              void* d_out, int out_size) {
    const float* h    = nullptr;   // 50331648
    const float* Wm   = nullptr;   // 19968
    const float* bias = nullptr;   // 26
    const int*   ids  = nullptr;   // 65536
    for (int i = 0; i < n_in; ++i) {
        switch (in_sizes[i]) {
            case BB * SS * DD: h    = (const float*)d_in[i]; break;
            case LL * DD:      Wm   = (const float*)d_in[i]; break;
            case LL:           bias = (const float*)d_in[i]; break;
            case BB * SS:      ids  = (const int*)d_in[i];   break;
        }
    }
    float* out = (float*)d_out;

    k_fused<<<NSEG, NTHR>>>(h, ids, Wm, bias, out);
}